// round 1
// baseline (speedup 1.0000x reference)
#include <cuda_runtime.h>
#include <cuda_bf16.h>
#include <cstdint>

// Problem constants
#define NN   40000
#define NE   640000
#define DIM  128
#define DO2  64

// ---------------- scratch (device globals; no allocation allowed) ----------
__device__ float g_agg[NN * DIM];
__device__ float g_h0[NN * DIM];
__device__ float g_h1[NN * DIM];
__device__ int   g_src[NE];
__device__ int   g_dst[NE];
__device__ int   g_edge64;

// ---------------- f32x2 packed-FMA helpers ---------------------------------
__device__ __forceinline__ unsigned long long pack2(float x, float y) {
    unsigned long long r;
    asm("mov.b64 %0, {%1, %2};" : "=l"(r) : "f"(x), "f"(y));
    return r;
}
__device__ __forceinline__ void unpack2(unsigned long long v, float& x, float& y) {
    asm("mov.b64 {%0, %1}, %2;" : "=f"(x), "=f"(y) : "l"(v));
}
__device__ __forceinline__ void fma2(unsigned long long& acc,
                                     unsigned long long a2,
                                     unsigned long long b2) {
    asm("fma.rn.f32x2 %0, %1, %2, %0;" : "+l"(acc) : "l"(a2), "l"(b2));
}

// ---------------- edge index dtype detection + conversion ------------------
// jnp.int64 without x64 enabled silently becomes int32; we cannot see
// metadata.txt, so detect at runtime: for int64 little-endian data with
// values in [0, 40000), every odd 32-bit word (high half) is 0.
__global__ void detect_kernel(const int* __restrict__ ei32) {
    if (blockIdx.x == 0 && threadIdx.x == 0) {
        int is64 = 1;
        #pragma unroll 1
        for (int i = 0; i < 64; i++) {
            if (ei32[2 * i + 1] != 0) { is64 = 0; break; }
        }
        g_edge64 = is64;
    }
}

__global__ void convert_edges_kernel(const void* __restrict__ ei, int E) {
    int i = blockIdx.x * blockDim.x + threadIdx.x;
    if (i >= E) return;
    if (g_edge64) {
        const long long* p = (const long long*)ei;
        g_src[i] = (int)p[i];
        g_dst[i] = (int)p[E + i];
    } else {
        const int* p = (const int*)ei;
        g_src[i] = p[i];
        g_dst[i] = p[E + i];
    }
}

// ---------------- zero fill -------------------------------------------------
__global__ void zero_kernel(float4* __restrict__ p, int n4) {
    int i = blockIdx.x * blockDim.x + threadIdx.x;
    if (i < n4) p[i] = make_float4(0.f, 0.f, 0.f, 0.f);
}

// ---------------- scatter-add aggregation ----------------------------------
// One warp per edge; each lane moves one float4 (128 dims = 32 float4).
// red.global.add.v4.f32: one 16B L2 reduction per lane (4x fewer atomic ops
// than scalar atomicAdd).
__global__ void scatter_kernel(const float4* __restrict__ h4,
                               float* __restrict__ agg, int E) {
    int gid = blockIdx.x * blockDim.x + threadIdx.x;
    int e = gid >> 5;
    if (e >= E) return;
    int c = gid & 31;
    int s = g_src[e];
    int d = g_dst[e];
    float4 v = h4[(size_t)s * 32 + c];
    float* p = agg + (size_t)d * DIM + c * 4;
    asm volatile("red.global.add.v4.f32 [%0], {%1, %2, %3, %4};"
                 :: "l"(p), "f"(v.x), "f"(v.y), "f"(v.z), "f"(v.w)
                 : "memory");
}

// ---------------- fused dual GEMM: relu(Aagg@Wr + br + Ah@Ws) --------------
// Concatenated-K SGEMM: K = 256 (first 128 from agg/Wr, next 128 from h/Ws).
// BM=128, BN=DO, BK=16. 256 threads (16x16), each computes 8 x (DO/16).
// Inner product uses fma.rn.f32x2 (2 MACs per FMA-pipe issue slot).
template <int DO>
__global__ void __launch_bounds__(256)
gemm_kernel(const float* __restrict__ Aagg, const float* __restrict__ Ah,
            const float* __restrict__ Wr, const float* __restrict__ br,
            const float* __restrict__ Ws, float* __restrict__ C, int M) {
    constexpr int BM = 128;
    constexpr int BK = 16;
    constexpr int TN = DO / 16;   // 8 for DO=128, 4 for DO=64
    constexpr int TN2 = TN / 2;

    __shared__ float As[BK][BM];
    __shared__ float Bs[BK][DO];

    const int tid = threadIdx.x;
    const int tx = tid & 15;
    const int ty = tid >> 4;
    const int m0 = blockIdx.x * BM;

    unsigned long long acc2[8][TN2];
    #pragma unroll
    for (int i = 0; i < 8; i++)
        #pragma unroll
        for (int j = 0; j < TN2; j++) acc2[i][j] = 0ULL;

    for (int kb = 0; kb < 2 * DIM; kb += BK) {
        const float* Asrc;
        const float* Bsrc;
        int kloc;
        if (kb < DIM) { Asrc = Aagg; Bsrc = Wr; kloc = kb; }
        else          { Asrc = Ah;   Bsrc = Ws; kloc = kb - DIM; }

        // Load A tile: BM rows x BK cols, transposed into As[k][m]
        #pragma unroll
        for (int i = 0; i < (BM * BK / 4) / 256; i++) {
            int f = tid + i * 256;              // 0..511
            int row = f >> 2;                   // BK/4 = 4 float4 per row
            int kq = (f & 3) * 4;
            float4 v = make_float4(0.f, 0.f, 0.f, 0.f);
            int gm = m0 + row;
            if (gm < M)
                v = *(const float4*)(Asrc + (size_t)gm * DIM + kloc + kq);
            As[kq + 0][row] = v.x;
            As[kq + 1][row] = v.y;
            As[kq + 2][row] = v.z;
            As[kq + 3][row] = v.w;
        }
        // Load B tile: BK rows x DO cols (row-major, direct)
        #pragma unroll
        for (int i = 0; i < (BK * DO / 4) / 256; i++) {
            int f = tid + i * 256;
            int row = f / (DO / 4);
            int col = (f % (DO / 4)) * 4;
            *(float4*)&Bs[row][col] =
                *(const float4*)(Bsrc + (size_t)(kloc + row) * DO + col);
        }
        __syncthreads();

        #pragma unroll
        for (int kk = 0; kk < BK; kk++) {
            float a[8];
            #pragma unroll
            for (int i = 0; i < 8; i++) a[i] = As[kk][ty * 8 + i];
            unsigned long long a2[8];
            #pragma unroll
            for (int i = 0; i < 8; i++) a2[i] = pack2(a[i], a[i]);
            unsigned long long b2[TN2];
            #pragma unroll
            for (int j = 0; j < TN2; j++) {
                float2 t = *(const float2*)&Bs[kk][tx * TN + 2 * j];
                b2[j] = pack2(t.x, t.y);
            }
            #pragma unroll
            for (int i = 0; i < 8; i++)
                #pragma unroll
                for (int j = 0; j < TN2; j++)
                    fma2(acc2[i][j], a2[i], b2[j]);
        }
        __syncthreads();
    }

    // Epilogue: + bias, ReLU, store
    float bias[TN];
    #pragma unroll
    for (int j = 0; j < TN; j++) bias[j] = br[tx * TN + j];

    #pragma unroll
    for (int i = 0; i < 8; i++) {
        int gm = m0 + ty * 8 + i;
        if (gm >= M) continue;
        float vals[TN];
        #pragma unroll
        for (int j = 0; j < TN2; j++)
            unpack2(acc2[i][j], vals[2 * j], vals[2 * j + 1]);
        #pragma unroll
        for (int j = 0; j < TN; j++) {
            float v = vals[j] + bias[j];
            vals[j] = v > 0.f ? v : 0.f;
        }
        float* out = C + (size_t)gm * DO + tx * TN;
        #pragma unroll
        for (int j = 0; j < TN; j += 4)
            *(float4*)(out + j) = make_float4(vals[j], vals[j + 1],
                                              vals[j + 2], vals[j + 3]);
    }
}

// ---------------- row-wise log_softmax over 64 cols (in place) -------------
__global__ void logsoftmax_kernel(float* __restrict__ io, int M) {
    int row = blockIdx.x * 8 + (threadIdx.x >> 5);
    if (row >= M) return;
    int lane = threadIdx.x & 31;
    float2* p = (float2*)io + (size_t)row * 32 + lane;
    float2 v = *p;
    float mx = fmaxf(v.x, v.y);
    #pragma unroll
    for (int o = 16; o > 0; o >>= 1)
        mx = fmaxf(mx, __shfl_xor_sync(0xffffffffu, mx, o));
    float s = expf(v.x - mx) + expf(v.y - mx);
    #pragma unroll
    for (int o = 16; o > 0; o >>= 1)
        s += __shfl_xor_sync(0xffffffffu, s, o);
    float lse = mx + logf(s);
    v.x -= lse;
    v.y -= lse;
    *p = v;
}

// ---------------- launch ----------------------------------------------------
extern "C" void kernel_launch(void* const* d_in, const int* in_sizes, int n_in,
                              void* d_out, int out_size) {
    const float* x   = (const float*)d_in[0];
    const void*  ei  = d_in[1];
    const float* Wr0 = (const float*)d_in[2];
    const float* br0 = (const float*)d_in[3];
    const float* Ws0 = (const float*)d_in[4];
    const float* Wr1 = (const float*)d_in[5];
    const float* br1 = (const float*)d_in[6];
    const float* Ws1 = (const float*)d_in[7];
    const float* Wr2 = (const float*)d_in[8];
    const float* br2 = (const float*)d_in[9];
    const float* Ws2 = (const float*)d_in[10];
    float* out = (float*)d_out;

    const int M = NN;
    const int E = NE;

    float *agg, *h0, *h1;
    cudaGetSymbolAddress((void**)&agg, g_agg);
    cudaGetSymbolAddress((void**)&h0, g_h0);
    cudaGetSymbolAddress((void**)&h1, g_h1);

    // Normalize edge index to int32 src/dst
    detect_kernel<<<1, 32>>>((const int*)ei);
    convert_edges_kernel<<<(E + 255) / 256, 256>>>(ei, E);

    const int n4 = NN * DIM / 4;
    const int zgrid = (n4 + 255) / 256;
    const int sgrid = (E * 32 + 255) / 256;
    const int ggrid = (M + 127) / 128;

    // Layer 0: x -> h0
    zero_kernel<<<zgrid, 256>>>((float4*)agg, n4);
    scatter_kernel<<<sgrid, 256>>>((const float4*)x, agg, E);
    gemm_kernel<DIM><<<ggrid, 256>>>(agg, x, Wr0, br0, Ws0, h0, M);

    // Layer 1: h0 -> h1
    zero_kernel<<<zgrid, 256>>>((float4*)agg, n4);
    scatter_kernel<<<sgrid, 256>>>((const float4*)h0, agg, E);
    gemm_kernel<DIM><<<ggrid, 256>>>(agg, h0, Wr1, br1, Ws1, h1, M);

    // Layer 2: h1 -> out (64-dim) + log_softmax
    zero_kernel<<<zgrid, 256>>>((float4*)agg, n4);
    scatter_kernel<<<sgrid, 256>>>((const float4*)h1, agg, E);
    gemm_kernel<DO2><<<ggrid, 256>>>(agg, h1, Wr2, br2, Ws2, out, M);
    logsoftmax_kernel<<<(M + 7) / 8, 256>>>(out, M);
}

// round 2
// speedup vs baseline: 1.0963x; 1.0963x over previous
#include <cuda_runtime.h>
#include <cuda_bf16.h>
#include <cstdint>

// Problem constants
#define NN   40000
#define NE   640000
#define DIM  128
#define DO2  64

// ---------------- scratch (device globals; no allocation allowed) ----------
__device__ float g_agg[NN * DIM];
__device__ float g_h0[NN * DIM];
__device__ float g_h1[NN * DIM];
__device__ int   g_src[NE];
__device__ int   g_dst[NE];
__device__ int   g_csr[NE];        // src ids grouped by dst
__device__ int   g_deg[NN];
__device__ int   g_rowptr[NN + 1];
__device__ int   g_cursor[NN];
__device__ int   g_edge64;

// ---------------- f32x2 packed-FMA helpers ---------------------------------
__device__ __forceinline__ unsigned long long pack2(float x, float y) {
    unsigned long long r;
    asm("mov.b64 %0, {%1, %2};" : "=l"(r) : "f"(x), "f"(y));
    return r;
}
__device__ __forceinline__ void unpack2(unsigned long long v, float& x, float& y) {
    asm("mov.b64 {%0, %1}, %2;" : "=f"(x), "=f"(y) : "l"(v));
}
__device__ __forceinline__ void fma2(unsigned long long& acc,
                                     unsigned long long a2,
                                     unsigned long long b2) {
    asm("fma.rn.f32x2 %0, %1, %2, %0;" : "+l"(acc) : "l"(a2), "l"(b2));
}

// ---------------- edge index dtype detection -------------------------------
__global__ void detect_kernel(const int* __restrict__ ei32) {
    if (blockIdx.x == 0 && threadIdx.x == 0) {
        int is64 = 1;
        #pragma unroll 1
        for (int i = 0; i < 64; i++) {
            if (ei32[2 * i + 1] != 0) { is64 = 0; break; }
        }
        g_edge64 = is64;
    }
}

__global__ void zero_deg_kernel(int n) {
    int i = blockIdx.x * blockDim.x + threadIdx.x;
    if (i < n) g_deg[i] = 0;
}

// Convert edge index to int32 src/dst AND count in-degrees.
__global__ void convert_edges_kernel(const void* __restrict__ ei, int E) {
    int i = blockIdx.x * blockDim.x + threadIdx.x;
    if (i >= E) return;
    int s, d;
    if (g_edge64) {
        const long long* p = (const long long*)ei;
        s = (int)p[i];
        d = (int)p[E + i];
    } else {
        const int* p = (const int*)ei;
        s = p[i];
        d = p[E + i];
    }
    g_src[i] = s;
    g_dst[i] = d;
    atomicAdd(&g_deg[d], 1);
}

// Single-block exclusive scan of g_deg -> g_rowptr (and g_cursor copy).
__global__ void __launch_bounds__(1024) scan_kernel(int n) {
    __shared__ int part[1024];
    int tid = threadIdx.x;
    int chunk = (n + 1023) / 1024;
    int start = tid * chunk;
    int end = start + chunk < n ? start + chunk : n;
    if (start > n) start = n;
    if (end < start) end = start;
    int s = 0;
    for (int i = start; i < end; i++) s += g_deg[i];
    part[tid] = s;
    __syncthreads();
    // inclusive Hillis-Steele scan
    for (int off = 1; off < 1024; off <<= 1) {
        int v = part[tid];
        int add = (tid >= off) ? part[tid - off] : 0;
        __syncthreads();
        part[tid] = v + add;
        __syncthreads();
    }
    int run = (tid == 0) ? 0 : part[tid - 1];
    for (int i = start; i < end; i++) {
        g_rowptr[i] = run;
        g_cursor[i] = run;
        run += g_deg[i];
    }
    if (tid == 1023) g_rowptr[n] = run;
}

// Bucket-fill CSR: csr[pos] = src for each edge, grouped by dst.
__global__ void fill_kernel(int E) {
    int i = blockIdx.x * blockDim.x + threadIdx.x;
    if (i >= E) return;
    int d = g_dst[i];
    int pos = atomicAdd(&g_cursor[d], 1);
    g_csr[pos] = g_src[i];
}

// ---------------- gather aggregation (one warp per node) -------------------
// Lane c accumulates float4 element c of each in-neighbor's row.
__global__ void gather_kernel(const float4* __restrict__ h4,
                              float4* __restrict__ agg, int M) {
    int node = blockIdx.x * (blockDim.x >> 5) + (threadIdx.x >> 5);
    if (node >= M) return;
    int lane = threadIdx.x & 31;
    int beg = g_rowptr[node];
    int end = g_rowptr[node + 1];
    float4 acc = make_float4(0.f, 0.f, 0.f, 0.f);
    int i = beg;
    for (; i + 3 < end; i += 4) {
        int s0 = g_csr[i], s1 = g_csr[i + 1], s2 = g_csr[i + 2], s3 = g_csr[i + 3];
        float4 v0 = __ldg(&h4[(size_t)s0 * 32 + lane]);
        float4 v1 = __ldg(&h4[(size_t)s1 * 32 + lane]);
        float4 v2 = __ldg(&h4[(size_t)s2 * 32 + lane]);
        float4 v3 = __ldg(&h4[(size_t)s3 * 32 + lane]);
        acc.x += (v0.x + v1.x) + (v2.x + v3.x);
        acc.y += (v0.y + v1.y) + (v2.y + v3.y);
        acc.z += (v0.z + v1.z) + (v2.z + v3.z);
        acc.w += (v0.w + v1.w) + (v2.w + v3.w);
    }
    for (; i < end; i++) {
        int s0 = g_csr[i];
        float4 v0 = __ldg(&h4[(size_t)s0 * 32 + lane]);
        acc.x += v0.x; acc.y += v0.y; acc.z += v0.z; acc.w += v0.w;
    }
    agg[(size_t)node * 32 + lane] = acc;
}

// ---------------- fused dual GEMM: relu(Aagg@Wr + br + Ah@Ws) --------------
template <int DO>
__global__ void __launch_bounds__(256)
gemm_kernel(const float* __restrict__ Aagg, const float* __restrict__ Ah,
            const float* __restrict__ Wr, const float* __restrict__ br,
            const float* __restrict__ Ws, float* __restrict__ C, int M) {
    constexpr int BM = 128;
    constexpr int BK = 16;
    constexpr int TN = DO / 16;   // 8 for DO=128, 4 for DO=64
    constexpr int TN2 = TN / 2;

    __shared__ float As[BK][BM];
    __shared__ float Bs[BK][DO];

    const int tid = threadIdx.x;
    const int tx = tid & 15;
    const int ty = tid >> 4;
    const int m0 = blockIdx.x * BM;

    unsigned long long acc2[8][TN2];
    #pragma unroll
    for (int i = 0; i < 8; i++)
        #pragma unroll
        for (int j = 0; j < TN2; j++) acc2[i][j] = 0ULL;

    for (int kb = 0; kb < 2 * DIM; kb += BK) {
        const float* Asrc;
        const float* Bsrc;
        int kloc;
        if (kb < DIM) { Asrc = Aagg; Bsrc = Wr; kloc = kb; }
        else          { Asrc = Ah;   Bsrc = Ws; kloc = kb - DIM; }

        // Load A tile: BM rows x BK cols, transposed into As[k][m]
        #pragma unroll
        for (int i = 0; i < (BM * BK / 4) / 256; i++) {
            int f = tid + i * 256;
            int row = f >> 2;
            int kq = (f & 3) * 4;
            float4 v = make_float4(0.f, 0.f, 0.f, 0.f);
            int gm = m0 + row;
            if (gm < M)
                v = *(const float4*)(Asrc + (size_t)gm * DIM + kloc + kq);
            As[kq + 0][row] = v.x;
            As[kq + 1][row] = v.y;
            As[kq + 2][row] = v.z;
            As[kq + 3][row] = v.w;
        }
        // Load B tile
        #pragma unroll
        for (int i = 0; i < (BK * DO / 4) / 256; i++) {
            int f = tid + i * 256;
            int row = f / (DO / 4);
            int col = (f % (DO / 4)) * 4;
            *(float4*)&Bs[row][col] =
                *(const float4*)(Bsrc + (size_t)(kloc + row) * DO + col);
        }
        __syncthreads();

        #pragma unroll
        for (int kk = 0; kk < BK; kk++) {
            float a[8];
            #pragma unroll
            for (int i = 0; i < 8; i++) a[i] = As[kk][ty * 8 + i];
            unsigned long long a2[8];
            #pragma unroll
            for (int i = 0; i < 8; i++) a2[i] = pack2(a[i], a[i]);
            unsigned long long b2[TN2];
            #pragma unroll
            for (int j = 0; j < TN2; j++) {
                float2 t = *(const float2*)&Bs[kk][tx * TN + 2 * j];
                b2[j] = pack2(t.x, t.y);
            }
            #pragma unroll
            for (int i = 0; i < 8; i++)
                #pragma unroll
                for (int j = 0; j < TN2; j++)
                    fma2(acc2[i][j], a2[i], b2[j]);
        }
        __syncthreads();
    }

    float bias[TN];
    #pragma unroll
    for (int j = 0; j < TN; j++) bias[j] = br[tx * TN + j];

    #pragma unroll
    for (int i = 0; i < 8; i++) {
        int gm = m0 + ty * 8 + i;
        if (gm >= M) continue;
        float vals[TN];
        #pragma unroll
        for (int j = 0; j < TN2; j++)
            unpack2(acc2[i][j], vals[2 * j], vals[2 * j + 1]);
        #pragma unroll
        for (int j = 0; j < TN; j++) {
            float v = vals[j] + bias[j];
            vals[j] = v > 0.f ? v : 0.f;
        }
        float* out = C + (size_t)gm * DO + tx * TN;
        #pragma unroll
        for (int j = 0; j < TN; j += 4)
            *(float4*)(out + j) = make_float4(vals[j], vals[j + 1],
                                              vals[j + 2], vals[j + 3]);
    }
}

// ---------------- row-wise log_softmax over 64 cols (in place) -------------
__global__ void logsoftmax_kernel(float* __restrict__ io, int M) {
    int row = blockIdx.x * 8 + (threadIdx.x >> 5);
    if (row >= M) return;
    int lane = threadIdx.x & 31;
    float2* p = (float2*)io + (size_t)row * 32 + lane;
    float2 v = *p;
    float mx = fmaxf(v.x, v.y);
    #pragma unroll
    for (int o = 16; o > 0; o >>= 1)
        mx = fmaxf(mx, __shfl_xor_sync(0xffffffffu, mx, o));
    float s = expf(v.x - mx) + expf(v.y - mx);
    #pragma unroll
    for (int o = 16; o > 0; o >>= 1)
        s += __shfl_xor_sync(0xffffffffu, s, o);
    float lse = mx + logf(s);
    v.x -= lse;
    v.y -= lse;
    *p = v;
}

// ---------------- launch ----------------------------------------------------
extern "C" void kernel_launch(void* const* d_in, const int* in_sizes, int n_in,
                              void* d_out, int out_size) {
    const float* x   = (const float*)d_in[0];
    const void*  ei  = d_in[1];
    const float* Wr0 = (const float*)d_in[2];
    const float* br0 = (const float*)d_in[3];
    const float* Ws0 = (const float*)d_in[4];
    const float* Wr1 = (const float*)d_in[5];
    const float* br1 = (const float*)d_in[6];
    const float* Ws1 = (const float*)d_in[7];
    const float* Wr2 = (const float*)d_in[8];
    const float* br2 = (const float*)d_in[9];
    const float* Ws2 = (const float*)d_in[10];
    float* out = (float*)d_out;

    const int M = NN;
    const int E = NE;

    float *agg, *h0, *h1;
    cudaGetSymbolAddress((void**)&agg, g_agg);
    cudaGetSymbolAddress((void**)&h0, g_h0);
    cudaGetSymbolAddress((void**)&h1, g_h1);

    // Build CSR (dst -> srcs)
    zero_deg_kernel<<<(M + 255) / 256, 256>>>(M);
    detect_kernel<<<1, 32>>>((const int*)ei);
    convert_edges_kernel<<<(E + 255) / 256, 256>>>(ei, E);
    scan_kernel<<<1, 1024>>>(M);
    fill_kernel<<<(E + 255) / 256, 256>>>(E);

    const int ggrid = (M + 127) / 128;
    const int agrid = (M + 7) / 8;   // 8 warps per 256-thread block

    // Layer 0: x -> h0
    gather_kernel<<<agrid, 256>>>((const float4*)x, (float4*)agg, M);
    gemm_kernel<DIM><<<ggrid, 256>>>(agg, x, Wr0, br0, Ws0, h0, M);

    // Layer 1: h0 -> h1
    gather_kernel<<<agrid, 256>>>((const float4*)h0, (float4*)agg, M);
    gemm_kernel<DIM><<<ggrid, 256>>>(agg, h0, Wr1, br1, Ws1, h1, M);

    // Layer 2: h1 -> out (64-dim) + log_softmax
    gather_kernel<<<agrid, 256>>>((const float4*)h1, (float4*)agg, M);
    gemm_kernel<DO2><<<ggrid, 256>>>(agg, h1, Wr2, br2, Ws2, out, M);
    logsoftmax_kernel<<<(M + 7) / 8, 256>>>(out, M);
}

// round 4
// speedup vs baseline: 1.3944x; 1.2718x over previous
#include <cuda_runtime.h>
#include <cuda_bf16.h>
#include <cstdint>

// Problem constants
#define NN   40000
#define NE   640000
#define DIM  128
#define DO2  64
#define ELLW 64      // max in-degree capacity (Poisson(16) over 40k nodes: safe)

// ---------------- scratch (device globals; no allocation allowed) ----------
__device__ float g_agg[NN * DIM];
__device__ float g_h0[NN * DIM];
__device__ float g_h1[NN * DIM];
__device__ int   g_ell[NN * ELLW];   // in-neighbor src ids per node
__device__ int   g_cnt[NN];          // in-degree / fill cursor
__device__ int   g_edge64;

// ---------------- f32x2 packed-FMA helpers ---------------------------------
__device__ __forceinline__ unsigned long long pack2(float x, float y) {
    unsigned long long r;
    asm("mov.b64 %0, {%1, %2};" : "=l"(r) : "f"(x), "f"(y));
    return r;
}
__device__ __forceinline__ void unpack2(unsigned long long v, float& x, float& y) {
    asm("mov.b64 {%0, %1}, %2;" : "=f"(x), "=f"(y) : "l"(v));
}
__device__ __forceinline__ void fma2(unsigned long long& acc,
                                     unsigned long long a2,
                                     unsigned long long b2) {
    asm("fma.rn.f32x2 %0, %1, %2, %0;" : "+l"(acc) : "l"(a2), "l"(b2));
}

// ---------------- edge index dtype detection -------------------------------
__global__ void detect_kernel(const int* __restrict__ ei32) {
    if (blockIdx.x == 0 && threadIdx.x == 0) {
        int is64 = 1;
        #pragma unroll 1
        for (int i = 0; i < 64; i++) {
            if (ei32[2 * i + 1] != 0) { is64 = 0; break; }
        }
        g_edge64 = is64;
    }
}

__global__ void zero_cnt_kernel(int n) {
    int i = blockIdx.x * blockDim.x + threadIdx.x;
    if (i < n) g_cnt[i] = 0;
}

// Convert edge index and scatter src ids into ELL buckets directly.
__global__ void build_ell_kernel(const void* __restrict__ ei, int E) {
    int i = blockIdx.x * blockDim.x + threadIdx.x;
    if (i >= E) return;
    int s, d;
    if (g_edge64) {
        const long long* p = (const long long*)ei;
        s = (int)p[i];
        d = (int)p[E + i];
    } else {
        const int* p = (const int*)ei;
        s = p[i];
        d = p[E + i];
    }
    int slot = atomicAdd(&g_cnt[d], 1);
    g_ell[d * ELLW + slot] = s;
}

// ---------------- gather aggregation (one warp per node) -------------------
// Lane c accumulates float4 element c of each in-neighbor's row.
__global__ void gather_kernel(const float4* __restrict__ h4,
                              float4* __restrict__ agg, int M) {
    int node = blockIdx.x * (blockDim.x >> 5) + (threadIdx.x >> 5);
    if (node >= M) return;
    int lane = threadIdx.x & 31;
    int deg = g_cnt[node];
    const int* __restrict__ idx = g_ell + node * ELLW;
    float4 acc = make_float4(0.f, 0.f, 0.f, 0.f);
    int i = 0;
    for (; i + 3 < deg; i += 4) {
        int4 s4 = *(const int4*)(idx + i);
        float4 v0 = __ldg(&h4[(size_t)s4.x * 32 + lane]);
        float4 v1 = __ldg(&h4[(size_t)s4.y * 32 + lane]);
        float4 v2 = __ldg(&h4[(size_t)s4.z * 32 + lane]);
        float4 v3 = __ldg(&h4[(size_t)s4.w * 32 + lane]);
        acc.x += (v0.x + v1.x) + (v2.x + v3.x);
        acc.y += (v0.y + v1.y) + (v2.y + v3.y);
        acc.z += (v0.z + v1.z) + (v2.z + v3.z);
        acc.w += (v0.w + v1.w) + (v2.w + v3.w);
    }
    for (; i < deg; i++) {
        int s0 = idx[i];
        float4 v0 = __ldg(&h4[(size_t)s0 * 32 + lane]);
        acc.x += v0.x; acc.y += v0.y; acc.z += v0.z; acc.w += v0.w;
    }
    agg[(size_t)node * 32 + lane] = acc;
}

// ---------------- fused dual GEMM: relu(Aagg@Wr + br + Ah@Ws) --------------
template <int DO>
__global__ void __launch_bounds__(256)
gemm_kernel(const float* __restrict__ Aagg, const float* __restrict__ Ah,
            const float* __restrict__ Wr, const float* __restrict__ br,
            const float* __restrict__ Ws, float* __restrict__ C, int M) {
    constexpr int BM = 128;
    constexpr int BK = 16;
    constexpr int TN = DO / 16;   // 8 for DO=128, 4 for DO=64
    constexpr int TN2 = TN / 2;

    __shared__ float As[BK][BM];
    __shared__ float Bs[BK][DO];

    const int tid = threadIdx.x;
    const int tx = tid & 15;
    const int ty = tid >> 4;
    const int m0 = blockIdx.x * BM;

    unsigned long long acc2[8][TN2];
    #pragma unroll
    for (int i = 0; i < 8; i++)
        #pragma unroll
        for (int j = 0; j < TN2; j++) acc2[i][j] = 0ULL;

    for (int kb = 0; kb < 2 * DIM; kb += BK) {
        const float* Asrc;
        const float* Bsrc;
        int kloc;
        if (kb < DIM) { Asrc = Aagg; Bsrc = Wr; kloc = kb; }
        else          { Asrc = Ah;   Bsrc = Ws; kloc = kb - DIM; }

        // Load A tile: BM rows x BK cols, transposed into As[k][m]
        #pragma unroll
        for (int i = 0; i < (BM * BK / 4) / 256; i++) {
            int f = tid + i * 256;
            int row = f >> 2;
            int kq = (f & 3) * 4;
            float4 v = make_float4(0.f, 0.f, 0.f, 0.f);
            int gm = m0 + row;
            if (gm < M)
                v = *(const float4*)(Asrc + (size_t)gm * DIM + kloc + kq);
            As[kq + 0][row] = v.x;
            As[kq + 1][row] = v.y;
            As[kq + 2][row] = v.z;
            As[kq + 3][row] = v.w;
        }
        // Load B tile
        #pragma unroll
        for (int i = 0; i < (BK * DO / 4) / 256; i++) {
            int f = tid + i * 256;
            int row = f / (DO / 4);
            int col = (f % (DO / 4)) * 4;
            *(float4*)&Bs[row][col] =
                *(const float4*)(Bsrc + (size_t)(kloc + row) * DO + col);
        }
        __syncthreads();

        #pragma unroll
        for (int kk = 0; kk < BK; kk++) {
            float a[8];
            #pragma unroll
            for (int i = 0; i < 8; i++) a[i] = As[kk][ty * 8 + i];
            unsigned long long a2[8];
            #pragma unroll
            for (int i = 0; i < 8; i++) a2[i] = pack2(a[i], a[i]);
            unsigned long long b2[TN2];
            #pragma unroll
            for (int j = 0; j < TN2; j++) {
                float2 t = *(const float2*)&Bs[kk][tx * TN + 2 * j];
                b2[j] = pack2(t.x, t.y);
            }
            #pragma unroll
            for (int i = 0; i < 8; i++)
                #pragma unroll
                for (int j = 0; j < TN2; j++)
                    fma2(acc2[i][j], a2[i], b2[j]);
        }
        __syncthreads();
    }

    float bias[TN];
    #pragma unroll
    for (int j = 0; j < TN; j++) bias[j] = br[tx * TN + j];

    #pragma unroll
    for (int i = 0; i < 8; i++) {
        int gm = m0 + ty * 8 + i;
        if (gm >= M) continue;
        float vals[TN];
        #pragma unroll
        for (int j = 0; j < TN2; j++)
            unpack2(acc2[i][j], vals[2 * j], vals[2 * j + 1]);
        #pragma unroll
        for (int j = 0; j < TN; j++) {
            float v = vals[j] + bias[j];
            vals[j] = v > 0.f ? v : 0.f;
        }
        float* out = C + (size_t)gm * DO + tx * TN;
        #pragma unroll
        for (int j = 0; j < TN; j += 4)
            *(float4*)(out + j) = make_float4(vals[j], vals[j + 1],
                                              vals[j + 2], vals[j + 3]);
    }
}

// ---------------- row-wise log_softmax over 64 cols (in place) -------------
__global__ void logsoftmax_kernel(float* __restrict__ io, int M) {
    int row = blockIdx.x * 8 + (threadIdx.x >> 5);
    if (row >= M) return;
    int lane = threadIdx.x & 31;
    float2* p = (float2*)io + (size_t)row * 32 + lane;
    float2 v = *p;
    float mx = fmaxf(v.x, v.y);
    #pragma unroll
    for (int o = 16; o > 0; o >>= 1)
        mx = fmaxf(mx, __shfl_xor_sync(0xffffffffu, mx, o));
    float s = expf(v.x - mx) + expf(v.y - mx);
    #pragma unroll
    for (int o = 16; o > 0; o >>= 1)
        s += __shfl_xor_sync(0xffffffffu, s, o);
    float lse = mx + logf(s);
    v.x -= lse;
    v.y -= lse;
    *p = v;
}

// ---------------- launch ----------------------------------------------------
extern "C" void kernel_launch(void* const* d_in, const int* in_sizes, int n_in,
                              void* d_out, int out_size) {
    const float* x   = (const float*)d_in[0];
    const void*  ei  = d_in[1];
    const float* Wr0 = (const float*)d_in[2];
    const float* br0 = (const float*)d_in[3];
    const float* Ws0 = (const float*)d_in[4];
    const float* Wr1 = (const float*)d_in[5];
    const float* br1 = (const float*)d_in[6];
    const float* Ws1 = (const float*)d_in[7];
    const float* Wr2 = (const float*)d_in[8];
    const float* br2 = (const float*)d_in[9];
    const float* Ws2 = (const float*)d_in[10];
    float* out = (float*)d_out;

    const int M = NN;
    const int E = NE;

    float *agg, *h0, *h1;
    cudaGetSymbolAddress((void**)&agg, g_agg);
    cudaGetSymbolAddress((void**)&h0, g_h0);
    cudaGetSymbolAddress((void**)&h1, g_h1);

    // Build ELL adjacency (dst -> srcs), no prefix scan needed
    zero_cnt_kernel<<<(M + 255) / 256, 256>>>(M);
    detect_kernel<<<1, 32>>>((const int*)ei);
    build_ell_kernel<<<(E + 255) / 256, 256>>>(ei, E);

    const int ggrid = (M + 127) / 128;
    const int agrid = (M + 7) / 8;   // 8 warps per 256-thread block

    // Layer 0: x -> h0
    gather_kernel<<<agrid, 256>>>((const float4*)x, (float4*)agg, M);
    gemm_kernel<DIM><<<ggrid, 256>>>(agg, x, Wr0, br0, Ws0, h0, M);

    // Layer 1: h0 -> h1
    gather_kernel<<<agrid, 256>>>((const float4*)h0, (float4*)agg, M);
    gemm_kernel<DIM><<<ggrid, 256>>>(agg, h0, Wr1, br1, Ws1, h1, M);

    // Layer 2: h1 -> out (64-dim) + log_softmax
    gather_kernel<<<agrid, 256>>>((const float4*)h1, (float4*)agg, M);
    gemm_kernel<DO2><<<ggrid, 256>>>(agg, h1, Wr2, br2, Ws2, out, M);
    logsoftmax_kernel<<<(M + 7) / 8, 256>>>(out, M);
}

// round 6
// speedup vs baseline: 2.3233x; 1.6662x over previous
#include <cuda_runtime.h>
#include <cuda_bf16.h>
#include <cstdint>

// Problem constants
#define NN   40000
#define NE   640000
#define DIM  128
#define DO2  64
#define ELLW 64      // max in-degree capacity (Poisson(16) over 40k nodes: safe)

// ---------------- scratch (device globals; no allocation allowed) ----------
__device__ float g_agg[NN * DIM];
__device__ float g_h0[NN * DIM];
__device__ float g_h1[NN * DIM];
__device__ int   g_ell[NN * ELLW];
__device__ int   g_cnt[NN];
__device__ int   g_edge64;
// transposed + bf16-split weights, layout [n][k], k = 0..255 (Wr rows | Ws rows)
__device__ __nv_bfloat16 g_wh0[128 * 256], g_wl0[128 * 256];
__device__ __nv_bfloat16 g_wh1[128 * 256], g_wl1[128 * 256];
__device__ __nv_bfloat16 g_wh2[64 * 256],  g_wl2[64 * 256];

// ---------------- helpers ---------------------------------------------------
__device__ __forceinline__ uint32_t smem_u32(const void* p) {
    uint32_t a;
    asm("{ .reg .u64 t; cvta.to.shared.u64 t, %1; cvt.u32.u64 %0, t; }"
        : "=r"(a) : "l"(p));
    return a;
}

// mma.sync m16n8k16 bf16 -> f32 (portable PTX, runs on HMMA pipe)
__device__ __forceinline__ void mma_bf16(float* c, const uint32_t* a,
                                         const uint32_t* b) {
    asm volatile(
        "mma.sync.aligned.m16n8k16.row.col.f32.bf16.bf16.f32 "
        "{%0,%1,%2,%3}, {%4,%5,%6,%7}, {%8,%9}, {%0,%1,%2,%3};"
        : "+f"(c[0]), "+f"(c[1]), "+f"(c[2]), "+f"(c[3])
        : "r"(a[0]), "r"(a[1]), "r"(a[2]), "r"(a[3]), "r"(b[0]), "r"(b[1]));
}

__device__ __forceinline__ void ldm4(uint32_t* r, uint32_t addr) {
    asm volatile("ldmatrix.sync.aligned.m8n8.x4.shared.b16 {%0,%1,%2,%3}, [%4];"
                 : "=r"(r[0]), "=r"(r[1]), "=r"(r[2]), "=r"(r[3]) : "r"(addr));
}

// Swizzled smem offset for a 256B-row bf16 tile: 16B chunk index XOR'd by row.
// k0 is the element column (multiple of 4).
__device__ __forceinline__ uint32_t sw_off(int r, int k0) {
    return (uint32_t)r * 256u + ((uint32_t)(((k0 >> 3) ^ (r & 7)) << 4))
         + (uint32_t)((k0 & 4) << 1);
}

// ---------------- edge index dtype detection -------------------------------
__global__ void detect_kernel(const int* __restrict__ ei32) {
    if (blockIdx.x == 0 && threadIdx.x == 0) {
        int is64 = 1;
        #pragma unroll 1
        for (int i = 0; i < 64; i++) {
            if (ei32[2 * i + 1] != 0) { is64 = 0; break; }
        }
        g_edge64 = is64;
    }
}

__global__ void zero_cnt_kernel(int n) {
    int i = blockIdx.x * blockDim.x + threadIdx.x;
    if (i < n) g_cnt[i] = 0;
}

__global__ void build_ell_kernel(const void* __restrict__ ei, int E) {
    int i = blockIdx.x * blockDim.x + threadIdx.x;
    if (i >= E) return;
    int s, d;
    if (g_edge64) {
        const long long* p = (const long long*)ei;
        s = (int)p[i];
        d = (int)p[E + i];
    } else {
        const int* p = (const int*)ei;
        s = p[i];
        d = p[E + i];
    }
    int slot = atomicAdd(&g_cnt[d], 1);
    g_ell[d * ELLW + slot] = s;
}

// ---------------- weight prep: transpose + bf16 hi/lo split ----------------
// k in [0,256): k<128 -> Wr[k][n], else Ws[k-128][n]. Output [n][k].
template <int DO>
__global__ void prep_w_kernel(const float* __restrict__ Wr,
                              const float* __restrict__ Ws,
                              __nv_bfloat16* __restrict__ Wh,
                              __nv_bfloat16* __restrict__ Wl) {
    int i = blockIdx.x * blockDim.x + threadIdx.x;
    if (i >= 256 * DO) return;
    int k = i % 256;
    int n = i / 256;
    float w = (k < 128) ? Wr[(size_t)k * DO + n] : Ws[(size_t)(k - 128) * DO + n];
    __nv_bfloat16 hi = __float2bfloat16(w);
    float lo = w - __bfloat162float(hi);
    Wh[(size_t)n * 256 + k] = hi;
    Wl[(size_t)n * 256 + k] = __float2bfloat16(lo);
}

// ---------------- gather aggregation (one warp per node) -------------------
__global__ void gather_kernel(const float4* __restrict__ h4,
                              float4* __restrict__ agg, int M) {
    int node = blockIdx.x * (blockDim.x >> 5) + (threadIdx.x >> 5);
    if (node >= M) return;
    int lane = threadIdx.x & 31;
    int deg = g_cnt[node];
    const int* __restrict__ idx = g_ell + node * ELLW;
    float4 acc = make_float4(0.f, 0.f, 0.f, 0.f);
    int i = 0;
    for (; i + 3 < deg; i += 4) {
        int4 s4 = *(const int4*)(idx + i);
        float4 v0 = __ldg(&h4[(size_t)s4.x * 32 + lane]);
        float4 v1 = __ldg(&h4[(size_t)s4.y * 32 + lane]);
        float4 v2 = __ldg(&h4[(size_t)s4.z * 32 + lane]);
        float4 v3 = __ldg(&h4[(size_t)s4.w * 32 + lane]);
        acc.x += (v0.x + v1.x) + (v2.x + v3.x);
        acc.y += (v0.y + v1.y) + (v2.y + v3.y);
        acc.z += (v0.z + v1.z) + (v2.z + v3.z);
        acc.w += (v0.w + v1.w) + (v2.w + v3.w);
    }
    for (; i < deg; i++) {
        int s0 = idx[i];
        float4 v0 = __ldg(&h4[(size_t)s0 * 32 + lane]);
        acc.x += v0.x; acc.y += v0.y; acc.z += v0.z; acc.w += v0.w;
    }
    agg[(size_t)node * 32 + lane] = acc;
}

// ---------------- mma.sync dual GEMM: relu(Aagg@Wr + br + Ah@Ws) -----------
// Split-bf16 (hi+lo), 3-term: D = Ahi*Bhi + Ahi*Blo + Alo*Bhi (fp32 accum).
// CTA tile 128 x DO, warp tile 64x32; K=256 as 2 chunks of 128 (agg | h).
template <int DO>
__global__ void __launch_bounds__(64 * (DO / 32))
mma_gemm_kernel(const float* __restrict__ Aagg, const float* __restrict__ Ah,
                const __nv_bfloat16* __restrict__ Wh,
                const __nv_bfloat16* __restrict__ Wl,
                const float* __restrict__ br, float* __restrict__ C, int M) {
    constexpr int WN = DO / 32;             // warps along N
    constexpr int THREADS = 64 * WN;
    constexpr int A_HI = 0;
    constexpr int A_LO = 32768;             // A chunk: 128x128 bf16 = 32KB
    constexpr int B_HI = 65536;
    constexpr int B_LO = 65536 + DO * 256;

    extern __shared__ char smem[];
    const uint32_t sb = smem_u32(smem);
    const int tid = threadIdx.x;
    const int lane = tid & 31;
    const int wid = tid >> 5;
    const int wm = wid / WN;                // 0..1
    const int wn = wid % WN;
    const int m0 = blockIdx.x * 128;

    float acc[4][4][4];
    #pragma unroll
    for (int i = 0; i < 4; i++)
        #pragma unroll
        for (int j = 0; j < 4; j++)
            #pragma unroll
            for (int q = 0; q < 4; q++) acc[i][j][q] = 0.f;

    #pragma unroll 1
    for (int ch = 0; ch < 2; ch++) {
        const float* __restrict__ Asrc = ch ? Ah : Aagg;

        // ---- fill A (fp32 -> bf16 hi/lo, swizzled) ----
        #pragma unroll
        for (int t = 0; t < 4096 / THREADS; t++) {
            int f = tid + t * THREADS;
            int row = f >> 5;
            int k0 = (f & 31) * 4;
            int gm = m0 + row;
            float4 v = make_float4(0.f, 0.f, 0.f, 0.f);
            if (gm < M) v = *(const float4*)(Asrc + (size_t)gm * DIM + k0);
            __nv_bfloat162 h01 = __floats2bfloat162_rn(v.x, v.y);
            __nv_bfloat162 h23 = __floats2bfloat162_rn(v.z, v.w);
            float lx = v.x - __bfloat162float(h01.x);
            float ly = v.y - __bfloat162float(h01.y);
            float lz = v.z - __bfloat162float(h23.x);
            float lw = v.w - __bfloat162float(h23.y);
            __nv_bfloat162 l01 = __floats2bfloat162_rn(lx, ly);
            __nv_bfloat162 l23 = __floats2bfloat162_rn(lz, lw);
            uint32_t off = sw_off(row, k0);
            *(uint2*)(smem + A_HI + off) =
                make_uint2(*(uint32_t*)&h01, *(uint32_t*)&h23);
            *(uint2*)(smem + A_LO + off) =
                make_uint2(*(uint32_t*)&l01, *(uint32_t*)&l23);
        }
        // ---- fill B (preconverted bf16 hi/lo, swizzled) ----
        #pragma unroll
        for (int t = 0; t < (DO * 32) / THREADS; t++) {
            int f = tid + t * THREADS;
            int n = f >> 5;
            int k0 = (f & 31) * 4;
            uint2 vh = *(const uint2*)(Wh + (size_t)n * 256 + ch * 128 + k0);
            uint2 vl = *(const uint2*)(Wl + (size_t)n * 256 + ch * 128 + k0);
            uint32_t off = sw_off(n, k0);
            *(uint2*)(smem + B_HI + off) = vh;
            *(uint2*)(smem + B_LO + off) = vl;
        }
        __syncthreads();

        // ---- MMA over 8 k16-steps ----
        #pragma unroll
        for (int ks = 0; ks < 8; ks++) {
            uint32_t ah[4][4], al[4][4], bh[2][4], bl[2][4];
            int ra = wm * 64 + (lane & 15);
            int hc = (lane >> 4) & 1;
            #pragma unroll
            for (int i = 0; i < 4; i++) {
                int r = ra + i * 16;
                uint32_t ad = sb + A_HI + (uint32_t)r * 256
                            + (uint32_t)((((ks * 2 + hc) ^ (r & 7))) << 4);
                ldm4(ah[i], ad);
                ldm4(al[i], ad + (A_LO - A_HI));
            }
            int nn = (lane & 7) | ((lane & 16) >> 1);
            int hb = (lane >> 3) & 1;
            #pragma unroll
            for (int p = 0; p < 2; p++) {
                int n = wn * 32 + p * 16 + nn;
                uint32_t bd = sb + B_HI + (uint32_t)n * 256
                            + (uint32_t)((((ks * 2 + hb) ^ (n & 7))) << 4);
                ldm4(bh[p], bd);
                ldm4(bl[p], bd + (B_LO - B_HI));
            }
            #pragma unroll
            for (int i = 0; i < 4; i++)
                #pragma unroll
                for (int j = 0; j < 4; j++) {
                    const uint32_t* bhp = &bh[j >> 1][(j & 1) * 2];
                    const uint32_t* blp = &bl[j >> 1][(j & 1) * 2];
                    mma_bf16(acc[i][j], ah[i], bhp);
                    mma_bf16(acc[i][j], ah[i], blp);
                    mma_bf16(acc[i][j], al[i], bhp);
                }
        }
        __syncthreads();
    }

    // ---- epilogue: + bias, ReLU, store ----
    const int cb = wn * 32 + (lane & 3) * 2;
    float2 bias[4];
    #pragma unroll
    for (int j = 0; j < 4; j++) bias[j] = *(const float2*)(br + cb + j * 8);
    const int rbase = m0 + wm * 64 + (lane >> 2);
    #pragma unroll
    for (int i = 0; i < 4; i++) {
        #pragma unroll
        for (int half = 0; half < 2; half++) {
            int r = rbase + i * 16 + half * 8;
            if (r < M) {
                float* outp = C + (size_t)r * DO;
                #pragma unroll
                for (int j = 0; j < 4; j++) {
                    float vx = acc[i][j][half * 2 + 0] + bias[j].x;
                    float vy = acc[i][j][half * 2 + 1] + bias[j].y;
                    *(float2*)(outp + cb + j * 8) =
                        make_float2(fmaxf(vx, 0.f), fmaxf(vy, 0.f));
                }
            }
        }
    }
}

// ---------------- row-wise log_softmax over 64 cols (in place) -------------
__global__ void logsoftmax_kernel(float* __restrict__ io, int M) {
    int row = blockIdx.x * 8 + (threadIdx.x >> 5);
    if (row >= M) return;
    int lane = threadIdx.x & 31;
    float2* p = (float2*)io + (size_t)row * 32 + lane;
    float2 v = *p;
    float mx = fmaxf(v.x, v.y);
    #pragma unroll
    for (int o = 16; o > 0; o >>= 1)
        mx = fmaxf(mx, __shfl_xor_sync(0xffffffffu, mx, o));
    float s = expf(v.x - mx) + expf(v.y - mx);
    #pragma unroll
    for (int o = 16; o > 0; o >>= 1)
        s += __shfl_xor_sync(0xffffffffu, s, o);
    float lse = mx + logf(s);
    v.x -= lse;
    v.y -= lse;
    *p = v;
}

// ---------------- launch ----------------------------------------------------
extern "C" void kernel_launch(void* const* d_in, const int* in_sizes, int n_in,
                              void* d_out, int out_size) {
    const float* x   = (const float*)d_in[0];
    const void*  ei  = d_in[1];
    const float* Wr0 = (const float*)d_in[2];
    const float* br0 = (const float*)d_in[3];
    const float* Ws0 = (const float*)d_in[4];
    const float* Wr1 = (const float*)d_in[5];
    const float* br1 = (const float*)d_in[6];
    const float* Ws1 = (const float*)d_in[7];
    const float* Wr2 = (const float*)d_in[8];
    const float* br2 = (const float*)d_in[9];
    const float* Ws2 = (const float*)d_in[10];
    float* out = (float*)d_out;

    const int M = NN;
    const int E = NE;

    float *agg, *h0, *h1;
    cudaGetSymbolAddress((void**)&agg, g_agg);
    cudaGetSymbolAddress((void**)&h0, g_h0);
    cudaGetSymbolAddress((void**)&h1, g_h1);
    __nv_bfloat16 *wh0, *wl0, *wh1, *wl1, *wh2, *wl2;
    cudaGetSymbolAddress((void**)&wh0, g_wh0);
    cudaGetSymbolAddress((void**)&wl0, g_wl0);
    cudaGetSymbolAddress((void**)&wh1, g_wh1);
    cudaGetSymbolAddress((void**)&wl1, g_wl1);
    cudaGetSymbolAddress((void**)&wh2, g_wh2);
    cudaGetSymbolAddress((void**)&wl2, g_wl2);

    const int smem128 = 65536 + 2 * 128 * 256;   // 131072
    const int smem64  = 65536 + 2 * 64 * 256;    // 98304
    cudaFuncSetAttribute(mma_gemm_kernel<128>,
                         cudaFuncAttributeMaxDynamicSharedMemorySize, smem128);
    cudaFuncSetAttribute(mma_gemm_kernel<64>,
                         cudaFuncAttributeMaxDynamicSharedMemorySize, smem64);

    // Build ELL adjacency + weight prep
    zero_cnt_kernel<<<(M + 255) / 256, 256>>>(M);
    detect_kernel<<<1, 32>>>((const int*)ei);
    build_ell_kernel<<<(E + 255) / 256, 256>>>(ei, E);
    prep_w_kernel<128><<<(256 * 128 + 255) / 256, 256>>>(Wr0, Ws0, wh0, wl0);
    prep_w_kernel<128><<<(256 * 128 + 255) / 256, 256>>>(Wr1, Ws1, wh1, wl1);
    prep_w_kernel<64><<<(256 * 64 + 255) / 256, 256>>>(Wr2, Ws2, wh2, wl2);

    const int ggrid = (M + 127) / 128;     // 313
    const int agrid = (M + 7) / 8;

    // Layer 0: x -> h0
    gather_kernel<<<agrid, 256>>>((const float4*)x, (float4*)agg, M);
    mma_gemm_kernel<128><<<ggrid, 256, smem128>>>(agg, x, wh0, wl0, br0, h0, M);

    // Layer 1: h0 -> h1
    gather_kernel<<<agrid, 256>>>((const float4*)h0, (float4*)agg, M);
    mma_gemm_kernel<128><<<ggrid, 256, smem128>>>(agg, h0, wh1, wl1, br1, h1, M);

    // Layer 2: h1 -> out (64-dim) + log_softmax
    gather_kernel<<<agrid, 256>>>((const float4*)h1, (float4*)agg, M);
    mma_gemm_kernel<64><<<ggrid, 128, smem64>>>(agg, h1, wh2, wl2, br2, out, M);
    logsoftmax_kernel<<<(M + 7) / 8, 256>>>(out, M);
}